// round 9
// baseline (speedup 1.0000x reference)
#include <cuda_runtime.h>
#include <cuda_fp16.h>
#include <cstdint>

// ---------------------------------------------------------------------------
// Problem constants
// ---------------------------------------------------------------------------
#define BB   2
#define LL   2048
#define DM   512
#define HH   8
#define KT   5
#define HW   64
#define MTOT (BB*LL)                  // 4096
#define NKV_ (HH*KT*HW)               // 2560
#define NQK  (DM + NKV_)              // 3072  (q then k)
#define KBASE (DM)                    // k starts at col 512 in PQK
#define KD   512

// ---------------------------------------------------------------------------
// Device scratch
// ---------------------------------------------------------------------------
__device__ __half g_Xh  [(size_t)MTOT * KD];      //  4.2 MB
__device__ __half g_Wh  [(size_t)(NQK + NKV_) * KD]; // 5.8 MB [qw;kw;vw]
__device__ __half g_OWh [(size_t)DM * KD];        //  0.5 MB
__device__ float  g_PQK [(size_t)MTOT * NQK];     // 50.3 MB fp32 q,k projections
__device__ __half g_PV  [(size_t)MTOT * NKV_];    // 21.0 MB fp16 v projections
__device__ __half g_ATTN[(size_t)MTOT * DM];      //  4.2 MB

// ---------------------------------------------------------------------------
// Helpers
// ---------------------------------------------------------------------------
__device__ __forceinline__ void ldm_x4(uint32_t& r0, uint32_t& r1, uint32_t& r2, uint32_t& r3,
                                       const void* p) {
    uint32_t a = (uint32_t)__cvta_generic_to_shared(p);
    asm volatile("ldmatrix.sync.aligned.m8n8.x4.shared.b16 {%0,%1,%2,%3}, [%4];"
                 : "=r"(r0), "=r"(r1), "=r"(r2), "=r"(r3) : "r"(a));
}

__device__ __forceinline__ void mma_fp16(float d[4], const uint32_t a[4], const uint32_t b[2]) {
    asm volatile(
        "mma.sync.aligned.m16n8k16.row.col.f32.f16.f16.f32 "
        "{%0,%1,%2,%3}, {%4,%5,%6,%7}, {%8,%9}, {%0,%1,%2,%3};\n"
        : "+f"(d[0]), "+f"(d[1]), "+f"(d[2]), "+f"(d[3])
        : "r"(a[0]), "r"(a[1]), "r"(a[2]), "r"(a[3]), "r"(b[0]), "r"(b[1]));
}

#define CP_ASYNC16(smem_ptr, gptr) \
    asm volatile("cp.async.cg.shared.global [%0], [%1], 16;\n" \
                 :: "r"((uint32_t)__cvta_generic_to_shared(smem_ptr)), "l"(gptr))

// ---------------------------------------------------------------------------
// K0: convert inputs to fp16
// ---------------------------------------------------------------------------
#define NX_  (MTOT*KD)
#define NQW_ (DM*KD)
#define NKW_ (NKV_*KD)
#define NW_  (NQW_ + 2*NKW_)
#define PREP_TOT (NX_ + NW_ + NQW_)

__global__ void prep_kernel(const float* __restrict__ x,
                            const float* __restrict__ qw,
                            const float* __restrict__ kw,
                            const float* __restrict__ vw,
                            const float* __restrict__ ow) {
    int i = blockIdx.x * blockDim.x + threadIdx.x;
    if (i >= PREP_TOT) return;
    if (i < NX_) {
        g_Xh[i] = __float2half_rn(x[i]);
    } else {
        int j = i - NX_;
        if (j < NW_) {
            float v;
            if (j < NQW_)             v = qw[j];
            else if (j < NQW_ + NKW_) v = kw[j - NQW_];
            else                      v = vw[j - NQW_ - NKW_];
            g_Wh[j] = __float2half_rn(v);
        } else {
            g_OWh[j - NW_] = __float2half_rn(ow[j - NW_]);
        }
    }
}

// ---------------------------------------------------------------------------
// fp16 GEMM: C[M][n0:n0+128] = A[M][512] * B[N][512]^T (+bias), fp32 accum.
// Template BMt (128 or 64): CTA tile BMt x 128, 8 warps (2x4),
// warp tile (BMt/2) x 32, BK=32, 3-stage cp.async, ldmatrix fragments.
// Stage row = 32 fp16 = 64 B = 4 x 16B chunks; smem stride 40 fp16 (80 B),
// 5*16B coprime 8 => conflict-free ldmatrix.
// ---------------------------------------------------------------------------
#define BN  128
#define BKH 32
#define SKH 40
#define NSTG 3

template <int BMt, typename OutT, bool HAS_BIAS>
__global__ __launch_bounds__(256, 2) void gemm_fp16(
    const __half* __restrict__ A, const __half* __restrict__ B,
    OutT* __restrict__ C, int ldc, const float* __restrict__ bias)
{
    extern __shared__ __half sh[];
    const int STG = (BMt + BN) * SKH;        // halfs per stage
    constexpr int MT = BMt / 32;             // m-frags per warp

    const int n0  = blockIdx.x * BN;
    const int m0  = blockIdx.y * BMt;
    const int tid = threadIdx.x;
    const int warp = tid >> 5, lane = tid & 31;
    const int wm = (warp >> 2) * (16 * MT);  // 0 / BMt/2
    const int wn = (warp & 3) * 32;
    const int g  = lane >> 2, t = lane & 3;

    float acc[MT][4][4];
    #pragma unroll
    for (int mt = 0; mt < MT; mt++)
        #pragma unroll
        for (int nt = 0; nt < 4; nt++)
            #pragma unroll
            for (int i = 0; i < 4; i++) acc[mt][nt][i] = 0.f;

    const __half* Ab = A + (size_t)m0 * KD;
    const __half* Bb = B + (size_t)n0 * KD;

    // Stage load: rows of 64 B = 4 chunks of 16 B. r = idx>>2, c = (idx&3)*8.
    auto load_stage = [&](int s, int k0) {
        __half* as = sh + (s % NSTG) * STG;
        __half* bs = as + BMt * SKH;
        #pragma unroll
        for (int i = 0; i < BMt / 64; ++i) {     // BMt*4 chunks of A
            int idx = tid + 256 * i;
            int r = idx >> 2, c = (idx & 3) * 8;
            CP_ASYNC16(&as[r * SKH + c], Ab + (size_t)r * KD + k0 + c);
        }
        #pragma unroll
        for (int i = 0; i < 2; ++i) {            // 512 chunks of B (128 rows)
            int idx = tid + 256 * i;
            int r = idx >> 2, c = (idx & 3) * 8;
            CP_ASYNC16(&bs[r * SKH + c], Bb + (size_t)r * KD + k0 + c);
        }
        asm volatile("cp.async.commit_group;\n" ::);
    };

    const int NKt = KD / BKH;   // 16
    load_stage(0, 0);
    load_stage(1, BKH);

    const int rowA  = lane & 15;
    const int kselA = ((lane >> 4) & 1) * 8;
    const int rowB  = lane & 7;
    const int nselB = ((lane >> 4) & 1) * 8;
    const int kselB = ((lane >> 3) & 1) * 8;

    for (int kt = 0; kt < NKt; ++kt) {
        if (kt + 2 < NKt) {
            load_stage(kt + 2, (kt + 2) * BKH);
            asm volatile("cp.async.wait_group 2;\n" ::);
        } else if (kt + 1 < NKt) {
            asm volatile("cp.async.wait_group 1;\n" ::);
        } else {
            asm volatile("cp.async.wait_group 0;\n" ::);
        }
        __syncthreads();

        const __half* as = sh + (kt % NSTG) * STG;
        const __half* bs = as + BMt * SKH;

        #pragma unroll
        for (int ch = 0; ch < 2; ++ch) {
            const int kb = ch * 16;
            uint32_t af[MT][4], bf[4][2];
            #pragma unroll
            for (int mt = 0; mt < MT; mt++)
                ldm_x4(af[mt][0], af[mt][1], af[mt][2], af[mt][3],
                       &as[(wm + mt * 16 + rowA) * SKH + kb + kselA]);
            #pragma unroll
            for (int p = 0; p < 2; p++)
                ldm_x4(bf[2*p][0], bf[2*p][1], bf[2*p+1][0], bf[2*p+1][1],
                       &bs[(wn + p * 16 + nselB + rowB) * SKH + kb + kselB]);
            #pragma unroll
            for (int mt = 0; mt < MT; mt++)
                #pragma unroll
                for (int nt = 0; nt < 4; nt++)
                    mma_fp16(acc[mt][nt], af[mt], bf[nt]);
        }
        __syncthreads();
    }

    // Epilogue: c0:(g,2t) c1:(g,2t+1) c2:(g+8,2t) c3:(g+8,2t+1)
    #pragma unroll
    for (int mt = 0; mt < MT; mt++) {
        int r = m0 + wm + mt * 16 + g;
        #pragma unroll
        for (int nt = 0; nt < 4; nt++) {
            int c = n0 + wn + nt * 8 + 2 * t;
            float o0 = acc[mt][nt][0], o1 = acc[mt][nt][1];
            float o2 = acc[mt][nt][2], o3 = acc[mt][nt][3];
            if (HAS_BIAS) {
                float b0 = bias[c], b1 = bias[c + 1];
                o0 += b0; o1 += b1; o2 += b0; o3 += b1;
            }
            if (sizeof(OutT) == 2) {
                __half2* p0 = (__half2*)((__half*)C + (size_t)(r    ) * ldc + c);
                __half2* p1 = (__half2*)((__half*)C + (size_t)(r + 8) * ldc + c);
                *p0 = __floats2half2_rn(o0, o1);
                *p1 = __floats2half2_rn(o2, o3);
            } else {
                *(float2*)((float*)C + (size_t)(r    ) * ldc + c) = make_float2(o0, o1);
                *(float2*)((float*)C + (size_t)(r + 8) * ldc + c) = make_float2(o2, o3);
            }
        }
    }
}

// ---------------------------------------------------------------------------
// K2: attention. One warp per (b,l,h). q,k gathered fp32 from PQK (logit-
// critical precision); v gathered fp16 from PV. Softmax over 5 taps,
// weighted V sum, /sqrt(64) -> fp16 ATTN. Lane i handles elements 2i, 2i+1.
// Out-of-range taps: content zero => k/v collapse to their biases.
// ---------------------------------------------------------------------------
__global__ __launch_bounds__(256) void attn_kernel(const float* __restrict__ qb,
                                                   const float* __restrict__ kb,
                                                   const float* __restrict__ vb) {
    int w    = (blockIdx.x * blockDim.x + threadIdx.x) >> 5;
    int lane = threadIdx.x & 31;
    if (w >= MTOT * HH) return;

    int h   = w & 7;
    int row = w >> 3;
    int l   = row & (LL - 1);
    int b   = row >> 11;
    int d   = 1 << (h & 3);

    const float2*  QK2 = (const float2*)g_PQK;
    const __half2* V2  = (const __half2*)g_PV;
    const int NQK2 = NQK / 2;       // 1536
    const int NV2  = NKV_ / 2;      // 1280
    int qoff = h * HW;
    int e0 = qoff + 2 * lane;

    float2 q = QK2[(size_t)row * NQK2 + (qoff >> 1) + lane];
    q.x += qb[e0]; q.y += qb[e0 + 1];

    float lg[KT];
    float2 vv[KT];
    #pragma unroll
    for (int kk = 0; kk < KT; ++kk) {
        int sl   = l + (kk - 2) * d;
        int kidx = (h * KT + kk) * HW;
        int be   = kidx + 2 * lane;
        float2 kf, vf;
        if (sl >= 0 && sl < LL) {
            int srow = b * LL + sl;
            kf = QK2[(size_t)srow * NQK2 + ((KBASE + kidx) >> 1) + lane];
            vf = __half22float2(V2[(size_t)srow * NV2 + (kidx >> 1) + lane]);
            kf.x += kb[be]; kf.y += kb[be + 1];
            vf.x += vb[be]; vf.y += vb[be + 1];
        } else {
            kf = make_float2(kb[be], kb[be + 1]);
            vf = make_float2(vb[be], vb[be + 1]);
        }
        vv[kk] = vf;
        float p = q.x * kf.x + q.y * kf.y;
        #pragma unroll
        for (int s = 16; s > 0; s >>= 1) p += __shfl_xor_sync(0xffffffffu, p, s);
        lg[kk] = p;
    }

    float mx = lg[0];
    #pragma unroll
    for (int kk = 1; kk < KT; ++kk) mx = fmaxf(mx, lg[kk]);
    float e[KT], se = 0.f;
    #pragma unroll
    for (int kk = 0; kk < KT; ++kk) { e[kk] = __expf(lg[kk] - mx); se += e[kk]; }
    float inv = 0.125f / se;             // includes /sqrt(HEAD_W)

    float a0 = 0.f, a1 = 0.f;
    #pragma unroll
    for (int kk = 0; kk < KT; ++kk) { a0 += e[kk] * vv[kk].x; a1 += e[kk] * vv[kk].y; }
    a0 *= inv; a1 *= inv;

    __half2* O2 = (__half2*)g_ATTN;
    O2[((size_t)row * DM + qoff) / 2 + lane] = __floats2half2_rn(a0, a1);
}

// ---------------------------------------------------------------------------
// Launch
// ---------------------------------------------------------------------------
extern "C" void kernel_launch(void* const* d_in, const int* in_sizes, int n_in,
                              void* d_out, int out_size) {
    const float* x   = (const float*)d_in[0];
    const float* q_w = (const float*)d_in[1];
    const float* q_b = (const float*)d_in[2];
    const float* k_w = (const float*)d_in[3];
    const float* k_b = (const float*)d_in[4];
    const float* v_w = (const float*)d_in[5];
    const float* v_b = (const float*)d_in[6];
    const float* o_w = (const float*)d_in[7];
    const float* o_b = (const float*)d_in[8];

    __half *Xh, *Wh, *OWh, *PV, *ATTN;
    float *PQK;
    cudaGetSymbolAddress((void**)&Xh,   g_Xh);
    cudaGetSymbolAddress((void**)&Wh,   g_Wh);
    cudaGetSymbolAddress((void**)&OWh,  g_OWh);
    cudaGetSymbolAddress((void**)&PQK,  g_PQK);
    cudaGetSymbolAddress((void**)&PV,   g_PV);
    cudaGetSymbolAddress((void**)&ATTN, g_ATTN);

    const int smem1 = NSTG * (128 + BN) * SKH * 2;   // 61440 B
    const int smem3 = NSTG * (64  + BN) * SKH * 2;   // 46080 B
    cudaFuncSetAttribute(gemm_fp16<128, float, false>,
                         cudaFuncAttributeMaxDynamicSharedMemorySize, smem1);
    cudaFuncSetAttribute(gemm_fp16<128, __half, false>,
                         cudaFuncAttributeMaxDynamicSharedMemorySize, smem1);
    cudaFuncSetAttribute(gemm_fp16<64, float, true>,
                         cudaFuncAttributeMaxDynamicSharedMemorySize, smem3);

    // K0: convert to fp16
    prep_kernel<<<(PREP_TOT + 255) / 256, 256>>>(x, q_w, k_w, v_w, o_w);

    // K1a: PQK[4096, 3072] = Xh @ [qw;kw]^T  (fp32 out: logit-critical)
    gemm_fp16<128, float, false><<<dim3(NQK / BN, MTOT / 128), 256, smem1>>>(
        Xh, Wh, PQK, NQK, nullptr);

    // K1b: PV[4096, 2560] = Xh @ vw^T  (fp16 out)
    gemm_fp16<128, __half, false><<<dim3(NKV_ / BN, MTOT / 128), 256, smem1>>>(
        Xh, Wh + (size_t)NQK * KD, PV, NKV_, nullptr);

    // K2: attention -> ATTN[4096, 512] fp16
    attn_kernel<<<(MTOT * HH * 32) / 256, 256>>>(q_b, k_b, v_b);

    // K3: OUT = ATTN @ OWh^T + o_b  (BM=64 -> 256 CTAs, fp32 out)
    gemm_fp16<64, float, true><<<dim3(DM / BN, MTOT / 64), 256, smem3>>>(
        ATTN, OWh, (float*)d_out, DM, o_b);
}

// round 10
// speedup vs baseline: 1.1283x; 1.1283x over previous
#include <cuda_runtime.h>
#include <cuda_fp16.h>
#include <cstdint>

// ---------------------------------------------------------------------------
// Problem constants
// ---------------------------------------------------------------------------
#define BB   2
#define LL   2048
#define DM   512
#define HH   8
#define KT   5
#define HW   64
#define MTOT (BB*LL)                  // 4096
#define NKV_ (HH*KT*HW)               // 2560
#define NQK  (DM + NKV_)              // 3072  (q then k)
#define NTOT (NQK + NKV_)             // 5632
#define KBASE (DM)                    // k starts at col 512 in PQK
#define KD   512

// ---------------------------------------------------------------------------
// Device scratch
// ---------------------------------------------------------------------------
__device__ __half g_Xh  [(size_t)MTOT * KD];      //  4.2 MB
__device__ __half g_Wh  [(size_t)NTOT * KD];      //  5.8 MB [qw;kw;vw]
__device__ __half g_OWh [(size_t)DM * KD];        //  0.5 MB
__device__ float  g_PQK [(size_t)MTOT * NQK];     // 50.3 MB fp32 q,k projections
__device__ __half g_PV  [(size_t)MTOT * NKV_];    // 21.0 MB fp16 v projections
__device__ __half g_ATTN[(size_t)MTOT * DM];      //  4.2 MB

// ---------------------------------------------------------------------------
// Helpers
// ---------------------------------------------------------------------------
__device__ __forceinline__ void ldm_x4(uint32_t& r0, uint32_t& r1, uint32_t& r2, uint32_t& r3,
                                       const void* p) {
    uint32_t a = (uint32_t)__cvta_generic_to_shared(p);
    asm volatile("ldmatrix.sync.aligned.m8n8.x4.shared.b16 {%0,%1,%2,%3}, [%4];"
                 : "=r"(r0), "=r"(r1), "=r"(r2), "=r"(r3) : "r"(a));
}

__device__ __forceinline__ void mma_fp16(float d[4], const uint32_t a[4], const uint32_t b[2]) {
    asm volatile(
        "mma.sync.aligned.m16n8k16.row.col.f32.f16.f16.f32 "
        "{%0,%1,%2,%3}, {%4,%5,%6,%7}, {%8,%9}, {%0,%1,%2,%3};\n"
        : "+f"(d[0]), "+f"(d[1]), "+f"(d[2]), "+f"(d[3])
        : "r"(a[0]), "r"(a[1]), "r"(a[2]), "r"(a[3]), "r"(b[0]), "r"(b[1]));
}

#define CP_ASYNC16(smem_ptr, gptr) \
    asm volatile("cp.async.cg.shared.global [%0], [%1], 16;\n" \
                 :: "r"((uint32_t)__cvta_generic_to_shared(smem_ptr)), "l"(gptr))

// ---------------------------------------------------------------------------
// K0: convert inputs to fp16
// ---------------------------------------------------------------------------
#define NX_  (MTOT*KD)
#define NQW_ (DM*KD)
#define NKW_ (NKV_*KD)
#define NW_  (NQW_ + 2*NKW_)
#define PREP_TOT (NX_ + NW_ + NQW_)

__global__ void prep_kernel(const float* __restrict__ x,
                            const float* __restrict__ qw,
                            const float* __restrict__ kw,
                            const float* __restrict__ vw,
                            const float* __restrict__ ow) {
    int i = blockIdx.x * blockDim.x + threadIdx.x;
    if (i >= PREP_TOT) return;
    if (i < NX_) {
        g_Xh[i] = __float2half_rn(x[i]);
    } else {
        int j = i - NX_;
        if (j < NW_) {
            float v;
            if (j < NQW_)             v = qw[j];
            else if (j < NQW_ + NKW_) v = kw[j - NQW_];
            else                      v = vw[j - NQW_ - NKW_];
            g_Wh[j] = __float2half_rn(v);
        } else {
            g_OWh[j - NW_] = __float2half_rn(ow[j - NW_]);
        }
    }
}

// ---------------------------------------------------------------------------
// fp16 GEMM, mixed-dtype output: blocks with n0 < NSPLIT write fp32 to C32
// (col n0), others write fp16 to C16 (col n0 - NSPLIT).
// CTA tile BMt x 128, 8 warps (2x4), warp tile (BMt/2) x 32, BK=32,
// 3-stage cp.async, ONE __syncthreads per K-iteration (cutlass ordering):
//   wait_group(1) -> sync -> issue stage kt+2 -> compute stage kt
// Safe: stage kt+2 == kt-1 (mod 3); its readers all passed this barrier.
// smem stride 40 fp16 (80 B): 5*16B coprime 8 => conflict-free ldmatrix.
// ---------------------------------------------------------------------------
#define BN  128
#define BKH 32
#define SKH 40
#define NSTG 3

template <int BMt, int NSPLIT, bool HAS_BIAS>
__global__ __launch_bounds__(256, 2) void gemm_fp16(
    const __half* __restrict__ A, const __half* __restrict__ B,
    float* __restrict__ C32, int ldc32,
    __half* __restrict__ C16, int ldc16,
    const float* __restrict__ bias)
{
    extern __shared__ __half sh[];
    const int STG = (BMt + BN) * SKH;        // halfs per stage
    constexpr int MT = BMt / 32;             // m-frags per warp

    const int n0  = blockIdx.x * BN;
    const int m0  = blockIdx.y * BMt;
    const int tid = threadIdx.x;
    const int warp = tid >> 5, lane = tid & 31;
    const int wm = (warp >> 2) * (16 * MT);  // 0 / BMt/2
    const int wn = (warp & 3) * 32;
    const int g  = lane >> 2, t = lane & 3;

    float acc[MT][4][4];
    #pragma unroll
    for (int mt = 0; mt < MT; mt++)
        #pragma unroll
        for (int nt = 0; nt < 4; nt++)
            #pragma unroll
            for (int i = 0; i < 4; i++) acc[mt][nt][i] = 0.f;

    const __half* Ab = A + (size_t)m0 * KD;
    const __half* Bb = B + (size_t)n0 * KD;

    // Stage load: rows of 64 B = 4 chunks of 16 B. r = idx>>2, c = (idx&3)*8.
    auto load_stage = [&](int s, int k0) {
        __half* as = sh + (s % NSTG) * STG;
        __half* bs = as + BMt * SKH;
        #pragma unroll
        for (int i = 0; i < BMt / 64; ++i) {     // BMt*4 chunks of A
            int idx = tid + 256 * i;
            int r = idx >> 2, c = (idx & 3) * 8;
            CP_ASYNC16(&as[r * SKH + c], Ab + (size_t)r * KD + k0 + c);
        }
        #pragma unroll
        for (int i = 0; i < 2; ++i) {            // 512 chunks of B (128 rows)
            int idx = tid + 256 * i;
            int r = idx >> 2, c = (idx & 3) * 8;
            CP_ASYNC16(&bs[r * SKH + c], Bb + (size_t)r * KD + k0 + c);
        }
        asm volatile("cp.async.commit_group;\n" ::);
    };

    const int NKt = KD / BKH;   // 16
    load_stage(0, 0);
    load_stage(1, BKH);

    const int rowA  = lane & 15;
    const int kselA = ((lane >> 4) & 1) * 8;
    const int rowB  = lane & 7;
    const int nselB = ((lane >> 4) & 1) * 8;
    const int kselB = ((lane >> 3) & 1) * 8;

    for (int kt = 0; kt < NKt; ++kt) {
        // stage kt ready (allow the one in-flight group for stage kt+1)
        if (kt + 1 < NKt) asm volatile("cp.async.wait_group 1;\n" ::);
        else              asm volatile("cp.async.wait_group 0;\n" ::);
        __syncthreads();               // single barrier per iteration

        if (kt + 2 < NKt) load_stage(kt + 2, (kt + 2) * BKH);

        const __half* as = sh + (kt % NSTG) * STG;
        const __half* bs = as + BMt * SKH;

        #pragma unroll
        for (int ch = 0; ch < 2; ++ch) {
            const int kb = ch * 16;
            uint32_t af[MT][4], bf[4][2];
            #pragma unroll
            for (int mt = 0; mt < MT; mt++)
                ldm_x4(af[mt][0], af[mt][1], af[mt][2], af[mt][3],
                       &as[(wm + mt * 16 + rowA) * SKH + kb + kselA]);
            #pragma unroll
            for (int p = 0; p < 2; p++)
                ldm_x4(bf[2*p][0], bf[2*p][1], bf[2*p+1][0], bf[2*p+1][1],
                       &bs[(wn + p * 16 + nselB + rowB) * SKH + kb + kselB]);
            #pragma unroll
            for (int mt = 0; mt < MT; mt++)
                #pragma unroll
                for (int nt = 0; nt < 4; nt++)
                    mma_fp16(acc[mt][nt], af[mt], bf[nt]);
        }
    }

    // Epilogue: c0:(g,2t) c1:(g,2t+1) c2:(g+8,2t) c3:(g+8,2t+1)
    const bool f32out = (n0 < NSPLIT);
    #pragma unroll
    for (int mt = 0; mt < MT; mt++) {
        int r = m0 + wm + mt * 16 + g;
        #pragma unroll
        for (int nt = 0; nt < 4; nt++) {
            int c = n0 + wn + nt * 8 + 2 * t;
            float o0 = acc[mt][nt][0], o1 = acc[mt][nt][1];
            float o2 = acc[mt][nt][2], o3 = acc[mt][nt][3];
            if (HAS_BIAS) {
                float b0 = bias[c], b1 = bias[c + 1];
                o0 += b0; o1 += b1; o2 += b0; o3 += b1;
            }
            if (f32out) {
                *(float2*)&C32[(size_t)(r    ) * ldc32 + c] = make_float2(o0, o1);
                *(float2*)&C32[(size_t)(r + 8) * ldc32 + c] = make_float2(o2, o3);
            } else {
                int c16 = c - NSPLIT;
                *(__half2*)&C16[(size_t)(r    ) * ldc16 + c16] = __floats2half2_rn(o0, o1);
                *(__half2*)&C16[(size_t)(r + 8) * ldc16 + c16] = __floats2half2_rn(o2, o3);
            }
        }
    }
}

// ---------------------------------------------------------------------------
// K2: attention. One warp per (b,l,h). q,k gathered fp32 from PQK (logit-
// critical precision); v gathered fp16 from PV. Softmax over 5 taps,
// weighted V sum, /sqrt(64) -> fp16 ATTN. Lane i handles elements 2i, 2i+1.
// Out-of-range taps: content zero => k/v collapse to their biases.
// ---------------------------------------------------------------------------
__global__ __launch_bounds__(256) void attn_kernel(const float* __restrict__ qb,
                                                   const float* __restrict__ kb,
                                                   const float* __restrict__ vb) {
    int w    = (blockIdx.x * blockDim.x + threadIdx.x) >> 5;
    int lane = threadIdx.x & 31;
    if (w >= MTOT * HH) return;

    int h   = w & 7;
    int row = w >> 3;
    int l   = row & (LL - 1);
    int b   = row >> 11;
    int d   = 1 << (h & 3);

    const float2*  QK2 = (const float2*)g_PQK;
    const __half2* V2  = (const __half2*)g_PV;
    const int NQK2 = NQK / 2;       // 1536
    const int NV2  = NKV_ / 2;      // 1280
    int qoff = h * HW;
    int e0 = qoff + 2 * lane;

    float2 q = QK2[(size_t)row * NQK2 + (qoff >> 1) + lane];
    q.x += qb[e0]; q.y += qb[e0 + 1];

    float lg[KT];
    float2 vv[KT];
    #pragma unroll
    for (int kk = 0; kk < KT; ++kk) {
        int sl   = l + (kk - 2) * d;
        int kidx = (h * KT + kk) * HW;
        int be   = kidx + 2 * lane;
        float2 kf, vf;
        if (sl >= 0 && sl < LL) {
            int srow = b * LL + sl;
            kf = QK2[(size_t)srow * NQK2 + ((KBASE + kidx) >> 1) + lane];
            vf = __half22float2(V2[(size_t)srow * NV2 + (kidx >> 1) + lane]);
            kf.x += kb[be]; kf.y += kb[be + 1];
            vf.x += vb[be]; vf.y += vb[be + 1];
        } else {
            kf = make_float2(kb[be], kb[be + 1]);
            vf = make_float2(vb[be], vb[be + 1]);
        }
        vv[kk] = vf;
        float p = q.x * kf.x + q.y * kf.y;
        #pragma unroll
        for (int s = 16; s > 0; s >>= 1) p += __shfl_xor_sync(0xffffffffu, p, s);
        lg[kk] = p;
    }

    float mx = lg[0];
    #pragma unroll
    for (int kk = 1; kk < KT; ++kk) mx = fmaxf(mx, lg[kk]);
    float e[KT], se = 0.f;
    #pragma unroll
    for (int kk = 0; kk < KT; ++kk) { e[kk] = __expf(lg[kk] - mx); se += e[kk]; }
    float inv = 0.125f / se;             // includes /sqrt(HEAD_W)

    float a0 = 0.f, a1 = 0.f;
    #pragma unroll
    for (int kk = 0; kk < KT; ++kk) { a0 += e[kk] * vv[kk].x; a1 += e[kk] * vv[kk].y; }
    a0 *= inv; a1 *= inv;

    __half2* O2 = (__half2*)g_ATTN;
    O2[((size_t)row * DM + qoff) / 2 + lane] = __floats2half2_rn(a0, a1);
}

// ---------------------------------------------------------------------------
// Launch
// ---------------------------------------------------------------------------
extern "C" void kernel_launch(void* const* d_in, const int* in_sizes, int n_in,
                              void* d_out, int out_size) {
    const float* x   = (const float*)d_in[0];
    const float* q_w = (const float*)d_in[1];
    const float* q_b = (const float*)d_in[2];
    const float* k_w = (const float*)d_in[3];
    const float* k_b = (const float*)d_in[4];
    const float* v_w = (const float*)d_in[5];
    const float* v_b = (const float*)d_in[6];
    const float* o_w = (const float*)d_in[7];
    const float* o_b = (const float*)d_in[8];

    __half *Xh, *Wh, *OWh, *PV, *ATTN;
    float *PQK;
    cudaGetSymbolAddress((void**)&Xh,   g_Xh);
    cudaGetSymbolAddress((void**)&Wh,   g_Wh);
    cudaGetSymbolAddress((void**)&OWh,  g_OWh);
    cudaGetSymbolAddress((void**)&PQK,  g_PQK);
    cudaGetSymbolAddress((void**)&PV,   g_PV);
    cudaGetSymbolAddress((void**)&ATTN, g_ATTN);

    const int smem1 = NSTG * (128 + BN) * SKH * 2;   // 61440 B
    const int smem3 = NSTG * (64  + BN) * SKH * 2;   // 46080 B
    cudaFuncSetAttribute(gemm_fp16<128, NQK, false>,
                         cudaFuncAttributeMaxDynamicSharedMemorySize, smem1);
    cudaFuncSetAttribute(gemm_fp16<64, DM, true>,
                         cudaFuncAttributeMaxDynamicSharedMemorySize, smem3);

    // K0: convert to fp16
    prep_kernel<<<(PREP_TOT + 255) / 256, 256>>>(x, q_w, k_w, v_w, o_w);

    // K1 (merged): cols 0..3071 -> PQK fp32, cols 3072..5631 -> PV fp16
    gemm_fp16<128, NQK, false><<<dim3(NTOT / BN, MTOT / 128), 256, smem1>>>(
        Xh, Wh, PQK, NQK, PV, NKV_, nullptr);

    // K2: attention -> ATTN[4096, 512] fp16
    attn_kernel<<<(MTOT * HH * 32) / 256, 256>>>(q_b, k_b, v_b);

    // K3: OUT = ATTN @ OWh^T + o_b  (BM=64 -> 256 CTAs, fp32 out)
    gemm_fp16<64, DM, true><<<dim3(DM / BN, MTOT / 64), 256, smem3>>>(
        ATTN, OWh, (float*)d_out, DM, (__half*)nullptr, 0, o_b);
}